// round 10
// baseline (speedup 1.0000x reference)
#include <cuda_runtime.h>
#include <cstdint>
#include <cstddef>

#define SEQ     2048
#define BATCH   128
#define HID     256
#define THREADS 512
#define NCHUNK  16            // 16-byte h chunks per 64-col window
#define MREG    10            // chunks whose W (2 pairs) lives in registers, per row
#define MSM     (NCHUNK-MREG) // 6 chunks per row served from smem
#define WIN     288           // h window stride: 256B data + 32B pad (bank-disjoint q's)
#define HSTRIDE 1152          // bytes per h parity buffer (4 windows * 288)

typedef unsigned long long u64;

__device__ __forceinline__ u64 ffma2(u64 a, u64 b, u64 c) {
    u64 d;
    asm("fma.rn.f32x2 %0, %1, %2, %3;" : "=l"(d) : "l"(a), "l"(b), "l"(c));
    return d;
}
__device__ __forceinline__ u64 add2(u64 a, u64 b) {
    u64 d;
    asm("add.rn.f32x2 %0, %1, %2;" : "=l"(d) : "l"(a), "l"(b));
    return d;
}
__device__ __forceinline__ float lo32(u64 v) { return __uint_as_float((unsigned)(v & 0xffffffffu)); }
__device__ __forceinline__ float hi32(u64 v) { return __uint_as_float((unsigned)(v >> 32)); }
__device__ __forceinline__ float fast_tanh(float x) {
    float r;
    asm("tanh.approx.f32 %0, %1;" : "=f"(r) : "f"(x));
    return r;
}
__device__ __forceinline__ u64 packf(float a, float b) {
    return (u64)__float_as_uint(a) | ((u64)__float_as_uint(b) << 32);
}
// h slot byte offset for hidden index j (32B pad every 64 floats)
__device__ __forceinline__ int hslot(int j) { return 4 * j + 32 * (j >> 6); }

// ---------------------------------------------------------------------------
// Persistent recurrence. One CTA per batch element, 512 threads.
// Thread tid: p = tid>>2 (row pair: rows p and p+128), q = tid&3 (col quarter,
// cols [64q, 64q+64)). Each h chunk read feeds 4 ffma2 (2 rows x 2 pairs).
// Per row: chunks 0..9 use register W (40 pairs/thread), 10..15 smem W
// (24 pairs/thread, LDS.128). Row sum = shfl_xor(1)+shfl_xor(2) over 4 lanes.
// One __syncthreads per step. W_eff built in the prologue from Whh/Whb.
// ---------------------------------------------------------------------------
__global__ void __launch_bounds__(THREADS, 1) rnn_kernel(
    const float* __restrict__ x,     const float* __restrict__ h0,
    const float* __restrict__ noise, const float* __restrict__ W_ih,
    const float* __restrict__ b_h,   const float* __restrict__ Whh,
    const float* __restrict__ Whb,   const void*  __restrict__ ctxp,
    float* __restrict__ h_out)
{
    extern __shared__ char smraw[];
    ulonglong2* Wsm2  = (ulonglong2*)smraw;                  // 2*MSM*THREADS*16B = 96 KB
    char*       hbase = smraw + 2 * MSM * THREADS * 16;      // 2 * HSTRIDE

    const int b   = blockIdx.x;
    const int tid = threadIdx.x;
    const int p   = tid >> 2;        // row pair index 0..127
    const int q   = tid & 3;         // column quarter
    const int r0  = p;
    const int r1  = p + 128;

    // context (int32/int64 low word, or float32 bit pattern)
    int iv = *(const int*)ctxp;
    const float ctx = (iv > -1000000 && iv < 1000000) ? (float)iv : *(const float*)ctxp;

    // ---- Stage W_eff slices: regs (chunks 0..MREG-1) + smem (MREG..15) ----
    u64 Wreg[2 * 2 * MREG];          // [row_sel*2*MREG + 2m(+1)]
#pragma unroll
    for (int rs = 0; rs < 2; rs++) {
        const int r = rs ? r1 : r0;
        const float* ph = Whh + (size_t)r * HID + 64 * q;
        const float* pb = Whb + (size_t)r * HID + 64 * q;
#pragma unroll
        for (int m = 0; m < NCHUNK; m++) {
            float4 a4 = *(const float4*)(ph + 4 * m);
            float4 b4 = *(const float4*)(pb + 4 * m);
            u64 w0 = packf(fmaf(ctx, b4.x, a4.x), fmaf(ctx, b4.y, a4.y));
            u64 w1 = packf(fmaf(ctx, b4.z, a4.z), fmaf(ctx, b4.w, a4.w));
            if (m < MREG) {
                Wreg[rs * 2 * MREG + 2 * m]     = w0;
                Wreg[rs * 2 * MREG + 2 * m + 1] = w1;
            } else {
                Wsm2[(rs * MSM + (m - MREG)) * THREADS + tid] = make_ulonglong2(w0, w1);
            }
        }
    }

    const float win0 = W_ih[r0], win1 = W_ih[r1];
    const float bh0  = b_h[r0],  bh1  = b_h[r1];
    const int   sl0  = hslot(r0), sl1 = hslot(r1);

    if (q == 0) {
        *(float*)(hbase + sl0) = h0[b * HID + r0];
        *(float*)(hbase + sl1) = h0[b * HID + r1];
    }
    __syncthreads();

    const float* np = noise + (size_t)b * HID;             // + t*BATCH*HID + row
    float*       op = h_out + (size_t)b * SEQ * HID;       // + t*HID + row
    const float* xp = x + b;

    for (int t = 0; t < SEQ; t++) {
        const int   par = t & 1;
        const char* hr  = hbase + par * HSTRIDE + q * WIN;        // read side
        char*       hw  = hbase + (par ^ 1) * HSTRIDE;            // write side

        // Prefetch streamed inputs early (consumed ~1000 cycles later).
        float nz0 = 0.0f, nz1 = 0.0f;
        if (q == 0) {
            nz0 = __ldg(np + (size_t)t * (BATCH * HID) + r0);
            nz1 = __ldg(np + (size_t)t * (BATCH * HID) + r1);
        }
        const float xv = __ldg(xp + t * BATCH);

        u64 a00 = 0, a01 = 0, a10 = 0, a11 = 0;

        // Register-W chunks 0..9: each h chunk feeds both rows.
#pragma unroll
        for (int m = 0; m < MREG; m++) {
            ulonglong2 hh = *(const ulonglong2*)(hr + m * 16);
            a00 = ffma2(Wreg[2 * m],               hh.x, a00);
            a01 = ffma2(Wreg[2 * m + 1],           hh.y, a01);
            a10 = ffma2(Wreg[2 * MREG + 2 * m],     hh.x, a10);
            a11 = ffma2(Wreg[2 * MREG + 2 * m + 1], hh.y, a11);
        }
        // Smem-W chunks 10..15.
#pragma unroll
        for (int m = 0; m < MSM; m++) {
            ulonglong2 hh = *(const ulonglong2*)(hr + (MREG + m) * 16);
            ulonglong2 w0 = Wsm2[m * THREADS + tid];
            ulonglong2 w1 = Wsm2[(MSM + m) * THREADS + tid];
            a00 = ffma2(w0.x, hh.x, a00);
            a01 = ffma2(w0.y, hh.y, a01);
            a10 = ffma2(w1.x, hh.x, a10);
            a11 = ffma2(w1.y, hh.y, a11);
        }

        // Fold packed accumulators, then combine the 4 column quarters.
        u64 f0 = add2(a00, a01), f1 = add2(a10, a11);
        float s0 = lo32(f0) + hi32(f0);
        float s1 = lo32(f1) + hi32(f1);
        s0 += __shfl_xor_sync(0xffffffffu, s0, 1);
        s1 += __shfl_xor_sync(0xffffffffu, s1, 1);
        s0 += __shfl_xor_sync(0xffffffffu, s0, 2);
        s1 += __shfl_xor_sync(0xffffffffu, s1, 2);

        if (q == 0) {
            float hv0 = fast_tanh(fmaf(xv, win0, s0) + bh0) + nz0;
            float hv1 = fast_tanh(fmaf(xv, win1, s1) + bh1) + nz1;
            *(float*)(hw + sl0) = hv0;            // publish next h
            *(float*)(hw + sl1) = hv1;
            op[(size_t)t * HID + r0] = hv0;       // out[b, t, r] (streaming)
            op[(size_t)t * HID + r1] = hv1;
        }
        __syncthreads();
    }
}

// ---------------------------------------------------------------------------
// Output head: y[b,t] = sigmoid(<out[b,t,:], W[0,:]> + b[0]).
// One warp per (b,t); streaming read of 256 MB — memory bound (~50 us).
// ---------------------------------------------------------------------------
__global__ void __launch_bounds__(256) head_kernel(
    const float* __restrict__ ho, const float* __restrict__ W,
    const float* __restrict__ bb, float* __restrict__ y)
{
    const int warp = (blockIdx.x * blockDim.x + threadIdx.x) >> 5;  // (b*SEQ + t)
    const int lane = threadIdx.x & 31;
    if (warp >= BATCH * SEQ) return;

    const float4* pv = (const float4*)(ho + (size_t)warp * HID);
    const float4* w4 = (const float4*)W;   // W[0,:] = first 256 floats

    float4 v0 = pv[lane],     v1 = pv[lane + 32];
    float4 w0 = w4[lane],     w1 = w4[lane + 32];

    float s = v0.x * w0.x;
    s = fmaf(v0.y, w0.y, s);  s = fmaf(v0.z, w0.z, s);  s = fmaf(v0.w, w0.w, s);
    s = fmaf(v1.x, w1.x, s);  s = fmaf(v1.y, w1.y, s);
    s = fmaf(v1.z, w1.z, s);  s = fmaf(v1.w, w1.w, s);

#pragma unroll
    for (int o = 16; o > 0; o >>= 1) s += __shfl_xor_sync(0xffffffffu, s, o);

    if (lane == 0)
        y[warp] = 1.0f / (1.0f + expf(-(s + bb[0])));
}

// ---------------------------------------------------------------------------
// Launch: inputs in metadata order
//   x, h0, noise, W_ih, W_hh, W_hh_bias, b_h, W, b, context
// Output: concat( y[:, :, 0] (BATCH,SEQ),  out (BATCH,SEQ,HID) ), fp32.
// ---------------------------------------------------------------------------
extern "C" void kernel_launch(void* const* d_in, const int* in_sizes, int n_in,
                              void* d_out, int out_size) {
    (void)in_sizes; (void)n_in; (void)out_size;
    const float* x    = (const float*)d_in[0];
    const float* h0   = (const float*)d_in[1];
    const float* nois = (const float*)d_in[2];
    const float* Wih  = (const float*)d_in[3];
    const float* Whh  = (const float*)d_in[4];
    const float* Whb  = (const float*)d_in[5];
    const float* bh   = (const float*)d_in[6];
    const float* W    = (const float*)d_in[7];
    const float* bb   = (const float*)d_in[8];
    const void*  ctx  = d_in[9];

    float* y  = (float*)d_out;
    float* ho = y + (size_t)BATCH * SEQ;

    const int smem_bytes = 2 * MSM * THREADS * 16   // 96 KB smem W (ulonglong2)
                         + 2 * HSTRIDE;             // padded h double buffer
    cudaFuncSetAttribute(rnn_kernel, cudaFuncAttributeMaxDynamicSharedMemorySize,
                         smem_bytes);

    rnn_kernel<<<BATCH, THREADS, smem_bytes>>>(x, h0, nois, Wih, bh,
                                               Whh, Whb, ctx, ho);

    const int nwarps  = BATCH * SEQ;                 // 262144
    const int nblocks = (nwarps * 32 + 255) / 256;   // 32768
    head_kernel<<<nblocks, 256>>>(ho, W, bb, y);
}

// round 11
// speedup vs baseline: 1.5874x; 1.5874x over previous
#include <cuda_runtime.h>
#include <cstdint>
#include <cstddef>

#define SEQ     2048
#define BATCH   128
#define HID     256
#define THREADS 512        // 2 threads per row: lane pair (even=half0, odd=half1)
#define KPH     64         // pairs per half-row (128 cols)
#define KREG2   40         // pairs in registers per thread (80 regs)
#define KSM2    24         // pairs from smem per thread (bf16: 12 u64 words)
#define WSMW    12         // u64 bf16 words per thread (2 pairs each)
#define HBYTES  1056       // bytes per h parity buffer: 512 + 16 pad + 512 (+16 slack)

typedef unsigned long long u64;

__device__ __forceinline__ u64 ffma2(u64 a, u64 b, u64 c) {
    u64 d;
    asm("fma.rn.f32x2 %0, %1, %2, %3;" : "=l"(d) : "l"(a), "l"(b), "l"(c));
    return d;
}
__device__ __forceinline__ u64 add2(u64 a, u64 b) {
    u64 d;
    asm("add.rn.f32x2 %0, %1, %2;" : "=l"(d) : "l"(a), "l"(b));
    return d;
}
__device__ __forceinline__ float lo32(u64 v) { return __uint_as_float((unsigned)(v & 0xffffffffu)); }
__device__ __forceinline__ float hi32(u64 v) { return __uint_as_float((unsigned)(v >> 32)); }
__device__ __forceinline__ float fast_tanh(float x) {
    float r;
    asm("tanh.approx.f32 %0, %1;" : "=f"(r) : "f"(x));
    return r;
}
__device__ __forceinline__ u64 packf(float a, float b) {
    return (u64)__float_as_uint(a) | ((u64)__float_as_uint(b) << 32);
}
// bf16x2: f_lo -> bits[15:0], f_hi -> bits[31:16]  (PTX: d = {cvt(a)=hi, cvt(b)=lo})
__device__ __forceinline__ unsigned bfpack(float f_lo, float f_hi) {
    unsigned r;
    asm("cvt.rn.bf16x2.f32 %0, %1, %2;" : "=r"(r) : "f"(f_hi), "f"(f_lo));
    return r;
}
// build u64 from two u32 halves (register-pair naming; ~free in SASS)
__device__ __forceinline__ u64 mk64(unsigned lo, unsigned hi) {
    u64 r;
    asm("mov.b64 %0, {%1, %2};" : "=l"(r) : "r"(lo), "r"(hi));
    return r;
}
// unpack u32 of 2 bf16 into a packed f32-pair u64 (2 ALU ops)
__device__ __forceinline__ u64 bf2f(unsigned v) {
    return mk64(v << 16, v & 0xffff0000u);
}

// ---------------------------------------------------------------------------
// Persistent recurrence: one CTA per batch element, 512 threads.
// Thread tid: row r = tid>>1, half = tid&1 owns 64 of the row's 128 W-pairs:
// 40 in fp32 registers, 24 from smem stored as bf16 (halved crossbar traffic;
// unpack = shift on the idle ALU pipe). Halves combine via shfl_xor(1) — one
// __syncthreads per step. W_eff built in the prologue from Whh/Whb/context.
// ---------------------------------------------------------------------------
__global__ void __launch_bounds__(THREADS, 1) rnn_kernel(
    const float* __restrict__ x,     const float* __restrict__ h0,
    const float* __restrict__ noise, const float* __restrict__ W_ih,
    const float* __restrict__ b_h,   const float* __restrict__ Whh,
    const float* __restrict__ Whb,   const void*  __restrict__ ctxp,
    float* __restrict__ h_out)
{
    extern __shared__ char smraw[];
    u64*  Wsb   = (u64*)smraw;                         // WSMW*THREADS u64 = 48 KB
    char* hbase = smraw + (size_t)WSMW * THREADS * 8;  // 2 * HBYTES

    const int b    = blockIdx.x;
    const int tid  = threadIdx.x;
    const int r    = tid >> 1;       // row 0..255
    const int half = tid & 1;        // j-half 0/1
    const int hoff = half * 528;     // byte offset of this half's h region

    // context (int32/int64 low word, or float32 bit pattern)
    int iv = *(const int*)ctxp;
    const float ctx = (iv > -1000000 && iv < 1000000) ? (float)iv : *(const float*)ctxp;

    // ---- Build W_eff slice: pairs 0..39 -> fp32 regs, 40..63 -> bf16 smem ----
    u64 Wreg[KREG2];
    {
        const float4* ph = (const float4*)(Whh + (size_t)r * HID + 128 * half);
        const float4* pb = (const float4*)(Whb + (size_t)r * HID + 128 * half);
#pragma unroll
        for (int m = 0; m < 32; m++) {               // 2 pairs per iteration
            float4 a4 = ph[m];
            float4 b4 = pb[m];
            float f0 = fmaf(ctx, b4.x, a4.x), f1 = fmaf(ctx, b4.y, a4.y);
            float f2 = fmaf(ctx, b4.z, a4.z), f3 = fmaf(ctx, b4.w, a4.w);
            if (m < KREG2 / 2) {
                Wreg[2 * m]     = packf(f0, f1);
                Wreg[2 * m + 1] = packf(f2, f3);
            } else {
                Wsb[(m - KREG2 / 2) * THREADS + tid] =
                    mk64(bfpack(f0, f1), bfpack(f2, f3));
            }
        }
    }

    const float win  = W_ih[r];
    const float bh   = b_h[r];
    // h slot for row r: halves of the h vector are padded apart by 16B.
    const int   slot = (r < 128) ? 4 * r : 528 + 4 * (r - 128);

    if (half == 0) *(float*)(hbase + slot) = h0[b * HID + r];
    __syncthreads();

    const float* np = noise + (size_t)b * HID + r;
    float*       op = h_out + (size_t)b * SEQ * HID + r;
    const float* xp = x + b;

    for (int t = 0; t < SEQ; t++) {
        const char* hc  = hbase + (t & 1) * HBYTES + hoff;          // read side
        char*       hnb = hbase + ((t & 1) ^ 1) * HBYTES;           // write side

        // Prefetch streamed inputs early (consumed ~500+ cycles later).
        float nz = 0.0f;
        if (half == 0) nz = __ldg(np + (size_t)t * (BATCH * HID));
        const float xv = __ldg(xp + t * BATCH);

        u64 a0 = 0, a1 = 0, a2 = 0, a3 = 0;

        // Register-W part: chunks 0..19 (pairs 0..39 of this half).
#pragma unroll
        for (int kk = 0; kk < KREG2 / 2; kk++) {
            ulonglong2 hh = *(const ulonglong2*)(hc + kk * 16);  // paired broadcast
            a0 = ffma2(Wreg[2 * kk],     hh.x, a0);
            a1 = ffma2(Wreg[2 * kk + 1], hh.y, a1);
        }
        // bf16 smem-W part: chunks 20..31 (pairs 40..63 of this half).
#pragma unroll
        for (int m = 0; m < WSMW; m++) {
            ulonglong2 hh = *(const ulonglong2*)(hc + (KREG2 / 2 + m) * 16);
            u64 wb = Wsb[m * THREADS + tid];                    // LDS.64, 2 bf16 pairs
            unsigned wlo = (unsigned)(wb & 0xffffffffu);
            unsigned whi = (unsigned)(wb >> 32);
            a2 = ffma2(bf2f(wlo), hh.x, a2);
            a3 = ffma2(bf2f(whi), hh.y, a3);
        }

        // Fold 4 packed accumulators, then combine halves warp-locally.
        u64 aa = add2(add2(a0, a1), add2(a2, a3));
        float s = lo32(aa) + hi32(aa);
        s += __shfl_xor_sync(0xffffffffu, s, 1);

        if (half == 0) {
            float pre = fmaf(xv, win, s) + bh;
            float hv  = fast_tanh(pre) + nz;
            *(float*)(hnb + slot) = hv;      // publish next h
            op[(size_t)t * HID]   = hv;      // out[b, t, r] (streaming)
        }
        __syncthreads();
    }
}

// ---------------------------------------------------------------------------
// Output head: y[b,t] = sigmoid(<out[b,t,:], W[0,:]> + b[0]).
// One warp per (b,t); streaming read of 256 MB — measured 42.9us @ 80% DRAM.
// ---------------------------------------------------------------------------
__global__ void __launch_bounds__(256) head_kernel(
    const float* __restrict__ ho, const float* __restrict__ W,
    const float* __restrict__ bb, float* __restrict__ y)
{
    const int warp = (blockIdx.x * blockDim.x + threadIdx.x) >> 5;  // (b*SEQ + t)
    const int lane = threadIdx.x & 31;
    if (warp >= BATCH * SEQ) return;

    const float4* pv = (const float4*)(ho + (size_t)warp * HID);
    const float4* w4 = (const float4*)W;   // W[0,:] = first 256 floats

    float4 v0 = pv[lane],     v1 = pv[lane + 32];
    float4 w0 = w4[lane],     w1 = w4[lane + 32];

    float s = v0.x * w0.x;
    s = fmaf(v0.y, w0.y, s);  s = fmaf(v0.z, w0.z, s);  s = fmaf(v0.w, w0.w, s);
    s = fmaf(v1.x, w1.x, s);  s = fmaf(v1.y, w1.y, s);
    s = fmaf(v1.z, w1.z, s);  s = fmaf(v1.w, w1.w, s);

#pragma unroll
    for (int o = 16; o > 0; o >>= 1) s += __shfl_xor_sync(0xffffffffu, s, o);

    if (lane == 0)
        y[warp] = 1.0f / (1.0f + expf(-(s + bb[0])));
}

// ---------------------------------------------------------------------------
// Launch: inputs in metadata order
//   x, h0, noise, W_ih, W_hh, W_hh_bias, b_h, W, b, context
// Output: concat( y[:, :, 0] (BATCH,SEQ),  out (BATCH,SEQ,HID) ), fp32.
// ---------------------------------------------------------------------------
extern "C" void kernel_launch(void* const* d_in, const int* in_sizes, int n_in,
                              void* d_out, int out_size) {
    (void)in_sizes; (void)n_in; (void)out_size;
    const float* x    = (const float*)d_in[0];
    const float* h0   = (const float*)d_in[1];
    const float* nois = (const float*)d_in[2];
    const float* Wih  = (const float*)d_in[3];
    const float* Whh  = (const float*)d_in[4];
    const float* Whb  = (const float*)d_in[5];
    const float* bh   = (const float*)d_in[6];
    const float* W    = (const float*)d_in[7];
    const float* bb   = (const float*)d_in[8];
    const void*  ctx  = d_in[9];

    float* y  = (float*)d_out;
    float* ho = y + (size_t)BATCH * SEQ;

    const int smem_bytes = WSMW * THREADS * (int)sizeof(u64)  // 48 KB bf16 W
                         + 2 * HBYTES;                        // padded h buffers
    cudaFuncSetAttribute(rnn_kernel, cudaFuncAttributeMaxDynamicSharedMemorySize,
                         smem_bytes);

    rnn_kernel<<<BATCH, THREADS, smem_bytes>>>(x, h0, nois, Wih, bh,
                                               Whh, Whb, ctx, ho);

    const int nwarps  = BATCH * SEQ;                 // 262144
    const int nblocks = (nwarps * 32 + 255) / 256;   // 32768
    head_kernel<<<nblocks, 256>>>(ho, W, bb, y);
}